// round 6
// baseline (speedup 1.0000x reference)
#include <cuda_runtime.h>

#define BB 2
#define NN 262144
#define SS 24
#define TOT (BB*NN)
#define EPSV 1e-4f
#define PAD 257

// ---- scratch (no allocation allowed; __device__ globals) ----
__device__ float g_wm[TOT];
__device__ float g_u[TOT];
__device__ float g_v[TOT];
__device__ float g_gT[25 * TOT];   // G transposed, SoA: g_gT[c*TOT+i]
__device__ float g_aT[24 * TOT];   // A_off transposed, SoA
__device__ double g_sums[3];       // [0]=sum|A|, [1]=sum(valid), [2]=sum(diff^2)

// ---------------------------------------------------------------------------
__device__ __forceinline__ float blockReduceSum(float v, float* sh) {
    int lane = threadIdx.x & 31;
    int wid  = threadIdx.x >> 5;
    #pragma unroll
    for (int o = 16; o > 0; o >>= 1) v += __shfl_down_sync(0xffffffffu, v, o);
    if (lane == 0) sh[wid] = v;
    __syncthreads();
    v = (threadIdx.x < 8) ? sh[threadIdx.x] : 0.f;
    if (wid == 0) {
        #pragma unroll
        for (int o = 4; o > 0; o >>= 1) v += __shfl_down_sync(0xffffffffu, v, o);
    }
    return v;
}

__device__ __forceinline__ void load_nbr24(const int* __restrict__ nbr,
                                           long long i, int* nn) {
    const int4* nb4 = (const int4*)(nbr + i * SS);
    #pragma unroll
    for (int k = 0; k < 6; k++) {
        int4 q = nb4[k];
        nn[4*k+0] = q.x; nn[4*k+1] = q.y; nn[4*k+2] = q.z; nn[4*k+3] = q.w;
    }
}

// ---------------------------------------------------------------------------
__global__ void k_zero() {
    if (threadIdx.x < 3) g_sums[threadIdx.x] = 0.0;
}

// DRAM-bound pass: wm = w*vm ; u = wm*G0 (plain store) ; |A| + valid ;
// transpose Ao -> g_aT (SoA) via smem.
__global__ __launch_bounds__(256) void k_init(const float* __restrict__ G,
                                              const float* __restrict__ Ad,
                                              const float* __restrict__ Ao,
                                              const float* __restrict__ w,
                                              const float* __restrict__ vm) {
    __shared__ float sh_a[24 * PAD];
    __shared__ float sh_red[8];
    int tid = threadIdx.x;
    int node0 = blockIdx.x * 256;
    long long i = node0 + tid;

    // stage Ao rows (coalesced reads), accumulate |A| partial on the fly
    float s = 0.f;
    const float* aBase = Ao + (long long)node0 * SS;
    #pragma unroll
    for (int k = 0; k < 24; k++) {
        int t = k * 256 + tid;
        float a = aBase[t];
        s += fabsf(a);
        sh_a[(t % 24) * PAD + t / 24] = a;
    }
    s += fabsf(Ad[i]);
    __syncthreads();

    // write transposed Ao (coalesced SoA stores)
    #pragma unroll
    for (int c = 0; c < 24; c++)
        g_aT[(long long)c * TOT + i] = sh_a[c * PAD + tid];

    float v   = vm[i];
    float wmv = w[i] * v;
    g_wm[i] = wmv;
    g_u[i]  = wmv * G[i * 25];          // diagonal of u, plain store (no zeroing)

    float ba = blockReduceSum(s, sh_red);
    if (tid == 0) atomicAdd(&g_sums[0], (double)ba);
    __syncthreads();
    float bv = blockReduceSum(v, sh_red);
    if (tid == 0) atomicAdd(&g_sums[1], (double)bv);
}

// Atomic-bound pass: u += G^T scatter (24 atomics/node) ;
// also write staged G rows out as SoA g_gT (hidden under atomics).
__global__ __launch_bounds__(256) void k_scatter(const float* __restrict__ G,
                                                 const int* __restrict__ nbr) {
    __shared__ float sh_g[25 * PAD];
    int tid = threadIdx.x;
    int node0 = blockIdx.x * 256;
    long long i = node0 + tid;
    int base = (i >= NN) ? NN : 0;

    const float* gBase = G + (long long)node0 * 25;
    #pragma unroll
    for (int k = 0; k < 25; k++) {
        int t = k * 256 + tid;
        sh_g[(t % 25) * PAD + t / 25] = gBase[t];
    }
    __syncthreads();

    // SoA writeout for the gather_v kernel (coalesced)
    #pragma unroll
    for (int c = 0; c < 25; c++)
        g_gT[(long long)c * TOT + i] = sh_g[c * PAD + tid];

    float wmv = g_wm[i];
    int nn[24];
    load_nbr24(nbr, i, nn);
    #pragma unroll
    for (int j = 0; j < SS; j++) {
        int nb = nn[j];
        if ((unsigned)nb < (unsigned)NN)
            atomicAdd(&g_u[base + nb], wmv * sh_g[(j + 1) * PAD + tid]);
    }
}

// Gather-bound: v = G u + eps*wm. No smem; coefficients via coalesced SoA.
__global__ __launch_bounds__(256) void k_gather_v(const int* __restrict__ nbr) {
    long long i = (long long)blockIdx.x * 256 + threadIdx.x;
    int base = (i >= NN) ? NN : 0;

    int nn[24];
    load_nbr24(nbr, i, nn);
    float xs[24];
    #pragma unroll
    for (int j = 0; j < SS; j++)
        xs[j] = ((unsigned)nn[j] < (unsigned)NN) ? g_u[base + nn[j]] : 0.f;

    float acc = g_u[i] * g_gT[i];                       // c = 0 (diag)
    #pragma unroll
    for (int j = 0; j < SS; j++)
        acc = fmaf(xs[j], g_gT[(long long)(j + 1) * TOT + i], acc);

    g_v[i] = acc + EPSV * g_wm[i];
}

// Gather-bound: y = A v ; z = y/norm ; accumulate diff^2. No coefficient smem.
__global__ __launch_bounds__(256) void k_gather_y(const float* __restrict__ Ad,
                                                  const float* __restrict__ vm,
                                                  const int* __restrict__ nbr) {
    __shared__ float sh_red[8];
    __shared__ float s_inv;
    int tid = threadIdx.x;
    long long i = (long long)blockIdx.x * 256 + tid;
    int base = (i >= NN) ? NN : 0;

    if (tid == 0) {
        double norm = g_sums[0] / (g_sums[1] * 25.0 + 1e-6);
        s_inv = (float)(1.0 / (norm + 1e-8));
    }
    __syncthreads();

    int nn[24];
    load_nbr24(nbr, i, nn);
    float xs[24];
    #pragma unroll
    for (int j = 0; j < SS; j++)
        xs[j] = ((unsigned)nn[j] < (unsigned)NN) ? g_v[base + nn[j]] : 0.f;

    float acc = g_v[i] * Ad[i];
    #pragma unroll
    for (int j = 0; j < SS; j++)
        acc = fmaf(xs[j], g_aT[(long long)j * TOT + i], acc);

    float z = acc * s_inv;
    float d = (z - g_wm[i]) * vm[i];
    float sred = blockReduceSum(d * d, sh_red);
    if (tid == 0) atomicAdd(&g_sums[2], (double)sred);
}

__global__ void k_final(float* out) {
    out[0] = (float)(g_sums[2] / (g_sums[1] + 1e-6));
}

// ---------------------------------------------------------------------------
extern "C" void kernel_launch(void* const* d_in, const int* in_sizes, int n_in,
                              void* d_out, int out_size) {
    const float* G   = (const float*)d_in[0];   // [2,N,25]
    const float* Ad  = (const float*)d_in[1];   // [2,N,1]
    const float* Ao  = (const float*)d_in[2];   // [2,N,24]
    const float* w   = (const float*)d_in[3];   // [2,N,1]
    const float* vm  = (const float*)d_in[4];   // [2,N,1]
    const int*   nbr = (const int*)d_in[5];     // [2,N,24] int32
    float* out = (float*)d_out;

    const int T = 256;
    const int nodeBlocks = TOT / T;             // 2048, exact

    k_zero    <<<1, 32>>>();
    k_init    <<<nodeBlocks, T>>>(G, Ad, Ao, w, vm);
    k_scatter <<<nodeBlocks, T>>>(G, nbr);
    k_gather_v<<<nodeBlocks, T>>>(nbr);
    k_gather_y<<<nodeBlocks, T>>>(Ad, vm, nbr);
    k_final   <<<1, 1>>>(out);
}